// round 8
// baseline (speedup 1.0000x reference)
#include <cuda_runtime.h>
#include <math_constants.h>

// SpatialAttention: out = x * hardsigmoid(conv3x3([mean_c(x); max_c(x)]))
// x: [16, 256, 128, 128] fp32, conv_w: [1, 2, 3, 3] fp32.
//
// SINGLE-LAUNCH pipelined kernel with INTERLEAVED block dispatch.
// Each group g = 64 stripes of [4 reduce(g) | 1 conv(g-1) | 64 mul(g-2)],
// so every resident window mixes DRAM readers (reduce) with DRAM writers
// (mul) -> read & write streams overlap continuously (R7's phase-contiguous
// layout alternated read-bursts with write-only periods).

#define BATCH 16
#define CH    256
#define HH    128
#define WW    128
#define HWSZ  (HH * WW)          // 16384
#define HW4   (HWSZ / 4)         // 4096 float4 cols per (b,c) plane
#define NCHNK 16                 // 1 batch per chunk (16 MiB x-slice)

#define COLS_PER_BLK 16
#define NGRP  16                 // channel groups per reduce block
#define CPS   (CH / NGRP)        // 16 channels per group

#define R_BLK 256                // reduce blocks per chunk
#define C_BLK 64                 // conv blocks per chunk
#define M_BLK 4096               // mul blocks per chunk
#define STRIPES 64
#define STRIPE_SZ 69             // 4 reduce + 1 conv + 64 mul
#define GRP_BLK (STRIPES * STRIPE_SZ)     // 4416
#define NGROUPS (NCHNK + 2)               // 18

__device__ float g_avg[BATCH * HWSZ];
__device__ float g_max[BATCH * HWSZ];
__device__ float g_att[BATCH * HWSZ];

// dependency counters (zero-init; last consumer resets for graph replay)
__device__ int g_cnt_r[NCHNK];
__device__ int g_cnt_c[NCHNK];
__device__ int g_pass_r[NCHNK];
__device__ int g_pass_c[NCHNK];

__device__ __forceinline__ void spin_wait(volatile int* p, int target) {
    if (threadIdx.x == 0) {
        while (*p < target) __nanosleep(128);
        __threadfence();                 // acquire
    }
    __syncthreads();
}

__global__ void __launch_bounds__(256, 6)
fused_kernel(const float* __restrict__ x, const float* __restrict__ wt,
             float* __restrict__ out) {
    __shared__ float4 ssum[256];
    __shared__ float4 smax[256];

    int g      = blockIdx.x / GRP_BLK;   // pipeline group 0..17
    int r      = blockIdx.x % GRP_BLK;
    int stripe = r / STRIPE_SZ;          // 0..63
    int lane   = r % STRIPE_SZ;          // 0..68
    int t      = threadIdx.x;

    if (lane < 4) {
        // ---------------- reduce: chunk g, block rb in 0..255 ----------------
        if (g >= NCHNK) return;
        int rb      = stripe * 4 + lane;
        int b       = g;
        int colBase = rb * COLS_PER_BLK;
        int col_l   = t & (COLS_PER_BLK - 1);
        int cg      = t >> 4;            // 0..15

        const float4* xp = reinterpret_cast<const float4*>(x)
                         + (size_t)b * CH * HW4 + (size_t)cg * CPS * HW4
                         + colBase + col_l;

        float4 s = make_float4(0.f, 0.f, 0.f, 0.f);
        float4 m = make_float4(-CUDART_INF_F, -CUDART_INF_F, -CUDART_INF_F, -CUDART_INF_F);

        #pragma unroll 8
        for (int c = 0; c < CPS; c++) {
            float4 v = xp[c * HW4];
            s.x += v.x; s.y += v.y; s.z += v.z; s.w += v.w;
            m.x = fmaxf(m.x, v.x); m.y = fmaxf(m.y, v.y);
            m.z = fmaxf(m.z, v.z); m.w = fmaxf(m.w, v.w);
        }
        ssum[t] = s; smax[t] = m;
        __syncthreads();

        #pragma unroll
        for (int off = 128; off >= COLS_PER_BLK; off >>= 1) {
            if (t < off) {
                float4 s2 = ssum[t + off], m2 = smax[t + off];
                float4 sa = ssum[t],       ma = smax[t];
                sa.x += s2.x; sa.y += s2.y; sa.z += s2.z; sa.w += s2.w;
                ma.x = fmaxf(ma.x, m2.x); ma.y = fmaxf(ma.y, m2.y);
                ma.z = fmaxf(ma.z, m2.z); ma.w = fmaxf(ma.w, m2.w);
                ssum[t] = sa; smax[t] = ma;
            }
            __syncthreads();
        }

        if (t < COLS_PER_BLK) {
            const float inv = 1.0f / (float)CH;
            float4 sa = ssum[t], ma = smax[t];
            float4 a = make_float4(sa.x * inv, sa.y * inv, sa.z * inv, sa.w * inv);
            reinterpret_cast<float4*>(g_avg)[b * HW4 + colBase + t] = a;
            reinterpret_cast<float4*>(g_max)[b * HW4 + colBase + t] = ma;
        }
        __syncthreads();
        if (t == 0) {
            __threadfence();             // release avg/max
            atomicAdd(&g_cnt_r[b], 1);
        }
    } else if (lane == 4) {
        // ---------------- conv: chunk g-1, block cb in 0..63 ----------------
        int b = g - 1;
        if (b < 0 || b >= NCHNK) return;

        spin_wait(&g_cnt_r[b], R_BLK);
        if (t == 0) {
            int old = atomicAdd(&g_pass_r[b], 1);
            if (old == C_BLK - 1) { g_cnt_r[b] = 0; g_pass_r[b] = 0; }
        }

        int idx = stripe * 256 + t;      // 0 .. HWSZ-1
        int h   = idx >> 7;
        int w   = idx & (WW - 1);

        const float* __restrict__ A = g_avg + b * HWSZ;
        const float* __restrict__ M = g_max + b * HWSZ;

        float acc = 0.f;
        #pragma unroll
        for (int kh = 0; kh < 3; kh++) {
            int hh = h + kh - 1;
            if (hh < 0 || hh >= HH) continue;
            #pragma unroll
            for (int kw = 0; kw < 3; kw++) {
                int ww = w + kw - 1;
                if (ww < 0 || ww >= WW) continue;
                int o = hh * WW + ww;
                acc += __ldg(&wt[kh * 3 + kw])     * A[o]
                     + __ldg(&wt[9 + kh * 3 + kw]) * M[o];
            }
        }
        float y = fminf(fmaxf(acc + 3.0f, 0.0f), 6.0f) * (1.0f / 6.0f);
        g_att[b * HWSZ + idx] = y;

        __syncthreads();
        if (t == 0) {
            __threadfence();             // release att
            atomicAdd(&g_cnt_c[b], 1);
        }
    } else {
        // ---------------- mul: chunk g-2, block mb in 0..4095 ----------------
        int b = g - 2;
        if (b < 0 || b >= NCHNK) return;

        spin_wait(&g_cnt_c[b], C_BLK);
        if (t == 0) {
            int old = atomicAdd(&g_pass_c[b], 1);
            if (old == M_BLK - 1) { g_cnt_c[b] = 0; g_pass_c[b] = 0; }
        }

        int mb  = stripe * 64 + (lane - 5);
        int idx = mb * 256 + t;          // 0 .. CH*HW4-1
        int col = idx & (HW4 - 1);

        size_t gidx = (size_t)b * CH * HW4 + idx;

        float4 v = __ldcs(reinterpret_cast<const float4*>(x) + gidx);
        float4 a = __ldg(reinterpret_cast<const float4*>(g_att) + (size_t)b * HW4 + col);

        v.x *= a.x; v.y *= a.y; v.z *= a.z; v.w *= a.w;
        __stcs(reinterpret_cast<float4*>(out) + gidx, v);
    }
}

extern "C" void kernel_launch(void* const* d_in, const int* in_sizes, int n_in,
                              void* d_out, int out_size) {
    const float* x  = (const float*)d_in[0];
    const float* wt = (const float*)d_in[1];
    float* out      = (float*)d_out;

    fused_kernel<<<NGROUPS * GRP_BLK, 256>>>(x, wt, out);   // one launch
}

// round 9
// speedup vs baseline: 1.3855x; 1.3855x over previous
#include <cuda_runtime.h>
#include <math_constants.h>

// SpatialAttention: out = x * hardsigmoid(conv3x3([mean_c(x); max_c(x)]))
// x: [16, 256, 128, 128] fp32, conv_w: [1, 2, 3, 3] fp32.
//
// TWO-STREAM pipelined version: per-chunk chain reduce->conv->mul is serial,
// chunks are independent. Even chunks on the capture (legacy) stream, odd
// chunks on a second non-blocking stream, fork/join via events (capturable
// pattern -> graph with two parallel branches). One stream's reduce (DRAM
// read) overlaps the other stream's mul (DRAM write) with NO spin-waits or
// atomics (R7/R8's intra-grid counters cost more than launch boundaries).

#define BATCH 16
#define CH    256
#define HH    128
#define WW    128
#define HWSZ  (HH * WW)          // 16384
#define HW4   (HWSZ / 4)         // 4096 float4 cols per (b,c) plane
#define NCHNK 16                 // 1 batch per chunk (16 MiB x-slice)

#define COLS_PER_BLK 16
#define NGRP  16                 // channel groups per reduce block
#define CPS   (CH / NGRP)        // 16 channels per group

#define R_BLK 256                // reduce blocks per chunk
#define C_BLK 64                 // conv blocks per chunk
#define M_BLK 4096               // mul blocks per chunk

__device__ float g_avg[BATCH * HWSZ];
__device__ float g_max[BATCH * HWSZ];
__device__ float g_att[BATCH * HWSZ];

// ---------------------------------------------------------------------------
__global__ void __launch_bounds__(256) reduce_kernel(const float* __restrict__ x, int b) {
    __shared__ float4 ssum[256];
    __shared__ float4 smax[256];

    int t       = threadIdx.x;
    int colBase = blockIdx.x * COLS_PER_BLK;
    int col_l   = t & (COLS_PER_BLK - 1);
    int cg      = t >> 4;                 // 0..15 channel group

    const float4* xp = reinterpret_cast<const float4*>(x)
                     + (size_t)b * CH * HW4 + (size_t)cg * CPS * HW4
                     + colBase + col_l;

    float4 s = make_float4(0.f, 0.f, 0.f, 0.f);
    float4 m = make_float4(-CUDART_INF_F, -CUDART_INF_F, -CUDART_INF_F, -CUDART_INF_F);

    #pragma unroll 8
    for (int c = 0; c < CPS; c++) {
        float4 v = xp[c * HW4];
        s.x += v.x; s.y += v.y; s.z += v.z; s.w += v.w;
        m.x = fmaxf(m.x, v.x); m.y = fmaxf(m.y, v.y);
        m.z = fmaxf(m.z, v.z); m.w = fmaxf(m.w, v.w);
    }
    ssum[t] = s; smax[t] = m;
    __syncthreads();

    #pragma unroll
    for (int off = 128; off >= COLS_PER_BLK; off >>= 1) {
        if (t < off) {
            float4 s2 = ssum[t + off], m2 = smax[t + off];
            float4 sa = ssum[t],       ma = smax[t];
            sa.x += s2.x; sa.y += s2.y; sa.z += s2.z; sa.w += s2.w;
            ma.x = fmaxf(ma.x, m2.x); ma.y = fmaxf(ma.y, m2.y);
            ma.z = fmaxf(ma.z, m2.z); ma.w = fmaxf(ma.w, m2.w);
            ssum[t] = sa; smax[t] = ma;
        }
        __syncthreads();
    }

    if (t < COLS_PER_BLK) {
        const float inv = 1.0f / (float)CH;
        float4 sa = ssum[t], ma = smax[t];
        float4 a = make_float4(sa.x * inv, sa.y * inv, sa.z * inv, sa.w * inv);
        reinterpret_cast<float4*>(g_avg)[b * HW4 + colBase + t] = a;
        reinterpret_cast<float4*>(g_max)[b * HW4 + colBase + t] = ma;
    }
}

// ---------------------------------------------------------------------------
__global__ void __launch_bounds__(256) conv_kernel(const float* __restrict__ wt, int b) {
    int idx = blockIdx.x * 256 + threadIdx.x;   // 0 .. HWSZ-1
    int h   = idx >> 7;
    int w   = idx & (WW - 1);

    const float* __restrict__ A = g_avg + b * HWSZ;
    const float* __restrict__ M = g_max + b * HWSZ;

    float acc = 0.f;
    #pragma unroll
    for (int kh = 0; kh < 3; kh++) {
        int hh = h + kh - 1;
        if (hh < 0 || hh >= HH) continue;
        #pragma unroll
        for (int kw = 0; kw < 3; kw++) {
            int ww = w + kw - 1;
            if (ww < 0 || ww >= WW) continue;
            int o = hh * WW + ww;
            acc += __ldg(&wt[kh * 3 + kw])     * A[o]
                 + __ldg(&wt[9 + kh * 3 + kw]) * M[o];
        }
    }
    float y = fminf(fmaxf(acc + 3.0f, 0.0f), 6.0f) * (1.0f / 6.0f);
    g_att[b * HWSZ + idx] = y;
}

// ---------------------------------------------------------------------------
__global__ void __launch_bounds__(256) mul_kernel(const float* __restrict__ x,
                                                  float* __restrict__ out, int b) {
    int idx = blockIdx.x * 256 + threadIdx.x;   // 0 .. CH*HW4-1
    int col = idx & (HW4 - 1);

    size_t gidx = (size_t)b * CH * HW4 + idx;

    float4 v = __ldcs(reinterpret_cast<const float4*>(x) + gidx);
    float4 a = __ldg(reinterpret_cast<const float4*>(g_att) + (size_t)b * HW4 + col);

    v.x *= a.x; v.y *= a.y; v.z *= a.z; v.w *= a.w;
    __stcs(reinterpret_cast<float4*>(out) + gidx, v);
}

// ---------------------------------------------------------------------------
extern "C" void kernel_launch(void* const* d_in, const int* in_sizes, int n_in,
                              void* d_out, int out_size) {
    const float* x  = (const float*)d_in[0];
    const float* wt = (const float*)d_in[1];
    float* out      = (float*)d_out;

    // One-time host resources (no device memory involved).
    static cudaStream_t sB = []() {
        cudaStream_t s;
        cudaStreamCreateWithFlags(&s, cudaStreamNonBlocking);
        return s;
    }();
    static cudaEvent_t evFork = []() {
        cudaEvent_t e;
        cudaEventCreateWithFlags(&e, cudaEventDisableTiming);
        return e;
    }();
    static cudaEvent_t evJoin = []() {
        cudaEvent_t e;
        cudaEventCreateWithFlags(&e, cudaEventDisableTiming);
        return e;
    }();

    // Fork: bring sB into the captured graph as a parallel branch.
    cudaEventRecord(evFork, 0);
    cudaStreamWaitEvent(sB, evFork, 0);

    // Even chunks on the capture stream, odd chunks on sB. Each stream's
    // per-chunk chain (reduce -> conv -> mul) is ordered by stream order;
    // the two streams run concurrently, mixing DRAM reads with writes.
    for (int b = 0; b < NCHNK; b++) {
        cudaStream_t s = (b & 1) ? sB : (cudaStream_t)0;
        reduce_kernel<<<R_BLK, 256, 0, s>>>(x, b);
        conv_kernel<<<C_BLK, 256, 0, s>>>(wt, b);
        mul_kernel<<<M_BLK, 256, 0, s>>>(x, out, b);
    }

    // Join: capture stream waits for sB's branch.
    cudaEventRecord(evJoin, sB);
    cudaStreamWaitEvent(0, evJoin, 0);
}

// round 10
// speedup vs baseline: 1.4701x; 1.0611x over previous
#include <cuda_runtime.h>
#include <math_constants.h>

// SpatialAttention: out = x * hardsigmoid(conv3x3([mean_c(x); max_c(x)]))
// x: [16, 256, 128, 128] fp32, conv_w: [1, 2, 3, 3] fp32.
//
// Two-stream pipelined structure (R9) + high-occupancy reduce:
// reduce blocks are 512 threads (32 channel-groups x 8 channels), same
// warp-level coalescing (2 x 256B segments per warp load) but 2x the
// resident warps -> 2x memory-level parallelism (R9 profile: reduce was
// 21% occupancy, 2.2 TB/s — the dominant cost).

#define BATCH 16
#define CH    256
#define HH    128
#define WW    128
#define HWSZ  (HH * WW)          // 16384
#define HW4   (HWSZ / 4)         // 4096 float4 cols per (b,c) plane
#define NCHNK 16                 // 1 batch per chunk (16 MiB x-slice)

#define COLS_PER_BLK 16
#define RTHREADS 512
#define NGRP  (RTHREADS / COLS_PER_BLK)   // 32 channel groups
#define CPS   (CH / NGRP)                 // 8 channels per group

#define R_BLK 256                // reduce blocks per chunk (HW4/16)
#define C_BLK 64                 // conv blocks per chunk
#define M_BLK 4096               // mul blocks per chunk

__device__ float g_avg[BATCH * HWSZ];
__device__ float g_max[BATCH * HWSZ];
__device__ float g_att[BATCH * HWSZ];

// ---------------------------------------------------------------------------
__global__ void __launch_bounds__(RTHREADS) reduce_kernel(const float* __restrict__ x, int b) {
    __shared__ float4 ssum[RTHREADS];
    __shared__ float4 smax[RTHREADS];

    int t       = threadIdx.x;
    int colBase = blockIdx.x * COLS_PER_BLK;
    int col_l   = t & (COLS_PER_BLK - 1);
    int cg      = t >> 4;                 // 0..31 channel group

    const float4* xp = reinterpret_cast<const float4*>(x)
                     + (size_t)b * CH * HW4 + (size_t)cg * CPS * HW4
                     + colBase + col_l;

    float4 s = make_float4(0.f, 0.f, 0.f, 0.f);
    float4 m = make_float4(-CUDART_INF_F, -CUDART_INF_F, -CUDART_INF_F, -CUDART_INF_F);

    #pragma unroll
    for (int c = 0; c < CPS; c++) {       // 8 independent loads in flight
        float4 v = xp[c * HW4];
        s.x += v.x; s.y += v.y; s.z += v.z; s.w += v.w;
        m.x = fmaxf(m.x, v.x); m.y = fmaxf(m.y, v.y);
        m.z = fmaxf(m.z, v.z); m.w = fmaxf(m.w, v.w);
    }
    ssum[t] = s; smax[t] = m;
    __syncthreads();

    #pragma unroll
    for (int off = RTHREADS / 2; off >= COLS_PER_BLK; off >>= 1) {
        if (t < off) {
            float4 s2 = ssum[t + off], m2 = smax[t + off];
            float4 sa = ssum[t],       ma = smax[t];
            sa.x += s2.x; sa.y += s2.y; sa.z += s2.z; sa.w += s2.w;
            ma.x = fmaxf(ma.x, m2.x); ma.y = fmaxf(ma.y, m2.y);
            ma.z = fmaxf(ma.z, m2.z); ma.w = fmaxf(ma.w, m2.w);
            ssum[t] = sa; smax[t] = ma;
        }
        __syncthreads();
    }

    if (t < COLS_PER_BLK) {
        const float inv = 1.0f / (float)CH;
        float4 sa = ssum[t], ma = smax[t];
        float4 a = make_float4(sa.x * inv, sa.y * inv, sa.z * inv, sa.w * inv);
        reinterpret_cast<float4*>(g_avg)[b * HW4 + colBase + t] = a;
        reinterpret_cast<float4*>(g_max)[b * HW4 + colBase + t] = ma;
    }
}

// ---------------------------------------------------------------------------
__global__ void __launch_bounds__(256) conv_kernel(const float* __restrict__ wt, int b) {
    int idx = blockIdx.x * 256 + threadIdx.x;   // 0 .. HWSZ-1
    int h   = idx >> 7;
    int w   = idx & (WW - 1);

    const float* __restrict__ A = g_avg + b * HWSZ;
    const float* __restrict__ M = g_max + b * HWSZ;

    float acc = 0.f;
    #pragma unroll
    for (int kh = 0; kh < 3; kh++) {
        int hh = h + kh - 1;
        if (hh < 0 || hh >= HH) continue;
        #pragma unroll
        for (int kw = 0; kw < 3; kw++) {
            int ww = w + kw - 1;
            if (ww < 0 || ww >= WW) continue;
            int o = hh * WW + ww;
            acc += __ldg(&wt[kh * 3 + kw])     * A[o]
                 + __ldg(&wt[9 + kh * 3 + kw]) * M[o];
        }
    }
    float y = fminf(fmaxf(acc + 3.0f, 0.0f), 6.0f) * (1.0f / 6.0f);
    g_att[b * HWSZ + idx] = y;
}

// ---------------------------------------------------------------------------
__global__ void __launch_bounds__(256) mul_kernel(const float* __restrict__ x,
                                                  float* __restrict__ out, int b) {
    int idx = blockIdx.x * 256 + threadIdx.x;   // 0 .. CH*HW4-1
    int col = idx & (HW4 - 1);

    size_t gidx = (size_t)b * CH * HW4 + idx;

    float4 v = __ldcs(reinterpret_cast<const float4*>(x) + gidx);
    float4 a = __ldg(reinterpret_cast<const float4*>(g_att) + (size_t)b * HW4 + col);

    v.x *= a.x; v.y *= a.y; v.z *= a.z; v.w *= a.w;
    __stcs(reinterpret_cast<float4*>(out) + gidx, v);
}

// ---------------------------------------------------------------------------
extern "C" void kernel_launch(void* const* d_in, const int* in_sizes, int n_in,
                              void* d_out, int out_size) {
    const float* x  = (const float*)d_in[0];
    const float* wt = (const float*)d_in[1];
    float* out      = (float*)d_out;

    static cudaStream_t sB = []() {
        cudaStream_t s;
        cudaStreamCreateWithFlags(&s, cudaStreamNonBlocking);
        return s;
    }();
    static cudaEvent_t evFork = []() {
        cudaEvent_t e;
        cudaEventCreateWithFlags(&e, cudaEventDisableTiming);
        return e;
    }();
    static cudaEvent_t evJoin = []() {
        cudaEvent_t e;
        cudaEventCreateWithFlags(&e, cudaEventDisableTiming);
        return e;
    }();

    // Fork second stream into the captured graph.
    cudaEventRecord(evFork, 0);
    cudaStreamWaitEvent(sB, evFork, 0);

    // Even chunks on capture stream, odd chunks on sB.
    for (int b = 0; b < NCHNK; b++) {
        cudaStream_t s = (b & 1) ? sB : (cudaStream_t)0;
        reduce_kernel<<<R_BLK, RTHREADS, 0, s>>>(x, b);
        conv_kernel<<<C_BLK, 256, 0, s>>>(wt, b);
        mul_kernel<<<M_BLK, 256, 0, s>>>(x, out, b);
    }

    // Join.
    cudaEventRecord(evJoin, sB);
    cudaStreamWaitEvent(0, evJoin, 0);
}